// round 2
// baseline (speedup 1.0000x reference)
#include <cuda_runtime.h>
#include <math.h>

#define BATCH 8
#define CH 64
#define HH 512
#define WW 512
#define LL (HH*WW)
#define DSTATE 16
#define CUT 2048
#define BN_EPS 1e-5f

typedef unsigned long long u64;

// scratch (device globals — no runtime allocation allowed)
__device__ float g_xp[(size_t)BATCH*CH*LL];   // post in_proj activation
__device__ float g_xc[(size_t)BATCH*CH*LL];   // post depthwise activation
__device__ float g_Bp[BATCH*DSTATE*CUT];      // B-projection (truncated)
__device__ float g_Sp[BATCH*DSTATE*CUT];      // prefix states (truncated)
__device__ float g_S [BATCH*DSTATE];          // steady-state state
__device__ float g_cv[BATCH*CH];              // wC @ steady state

__device__ __forceinline__ float fsig(float x){ return 1.0f/(1.0f+__expf(-x)); }

// packed f32x2 FMA (Blackwell-only; 2x fp32 FMA throughput, full precision)
__device__ __forceinline__ u64 ffma2(u64 a, u64 b, u64 c){
  u64 d; asm("fma.rn.f32x2 %0, %1, %2, %3;" : "=l"(d) : "l"(a), "l"(b), "l"(c));
  return d;
}
__device__ __forceinline__ u64 fpack2(float lo, float hi){
  u64 r; asm("mov.b64 %0, {%1, %2};" : "=l"(r) : "f"(lo), "f"(hi)); return r;
}
__device__ __forceinline__ void funpack2(u64 v, float& lo, float& hi){
  asm("mov.b64 {%0, %1}, %2;" : "=f"(lo), "=f"(hi) : "l"(v));
}

// ---------------------------------------------------------------------------
// K1: xp = silu(bn(w_in @ x)).  128 pixels/block, 256 threads.
// f32x2 packed over pixel pairs; weights duplicated {w,w} in smem.
// ---------------------------------------------------------------------------
__global__ __launch_bounds__(256,2) void k_inproj(
    const float* __restrict__ x, const float* __restrict__ w_in,
    const float* __restrict__ gin, const float* __restrict__ bin)
{
  extern __shared__ float sm[];
  float* Wt2 = sm;           // [64][132] duplicated transposed weights
  float* xs  = sm + 64*132;  // [64][132] input tile
  const int tid = threadIdx.x;
  const int b = blockIdx.y;
  const long p0 = (long)blockIdx.x * 128;

  for (int idx = tid; idx < 64*64; idx += 256) {
    int o = idx >> 6, i = idx & 63;
    float v = w_in[idx];
    Wt2[i*132 + 2*o]     = v;
    Wt2[i*132 + 2*o + 1] = v;
  }
  const float* xb = x + (long)b*CH*LL + p0;
  for (int idx = tid; idx < 64*32; idx += 256) {
    int row = idx >> 5, c4 = idx & 31;
    *(float4*)(xs + row*132 + (c4<<2)) = *(const float4*)(xb + (long)row*LL + (c4<<2));
  }
  __syncthreads();

  const int og = tid >> 5, pg = tid & 31;
  u64 acc[8][2];
  #pragma unroll
  for (int q=0;q<8;q++){ acc[q][0]=0ull; acc[q][1]=0ull; }

  #pragma unroll 8
  for (int i=0;i<64;i++){
    const u64* xp2 = (const u64*)(xs + i*132 + (pg<<2));
    u64 x01 = xp2[0], x23 = xp2[1];
    const u64* wp2 = (const u64*)(Wt2 + i*132 + (og<<4));
    #pragma unroll
    for (int q=0;q<8;q++){
      u64 w = wp2[q];
      acc[q][0] = ffma2(w, x01, acc[q][0]);
      acc[q][1] = ffma2(w, x23, acc[q][1]);
    }
  }

  const float rs = rsqrtf(1.0f + BN_EPS);
  #pragma unroll
  for (int q=0;q<8;q++){
    int o = (og<<3)+q;
    float sc = gin[o]*rs, be = bin[o];
    float v0,v1,v2,v3;
    funpack2(acc[q][0], v0, v1);
    funpack2(acc[q][1], v2, v3);
    v0 = fmaf(v0,sc,be); v1 = fmaf(v1,sc,be);
    v2 = fmaf(v2,sc,be); v3 = fmaf(v3,sc,be);
    float4 r = make_float4(v0*fsig(v0), v1*fsig(v1), v2*fsig(v2), v3*fsig(v3));
    *(float4*)(g_xp + (long)(b*CH+o)*LL + p0 + (pg<<2)) = r;
  }
}

// ---------------------------------------------------------------------------
// K2: xc = silu(bn(depthwise3x3(xp))). 16 rows/block per (b, c).
// ---------------------------------------------------------------------------
__global__ __launch_bounds__(128) void k_dwconv(
    const float* __restrict__ wdw, const float* __restrict__ gcv,
    const float* __restrict__ bcv)
{
  __shared__ float s[18*512];
  const int tid = threadIdx.x;
  const int b = blockIdx.z, c = blockIdx.y, h0 = blockIdx.x*16;
  const float* xpc = g_xp + (long)(b*CH+c)*LL;

  #pragma unroll
  for (int r=0;r<18;r++){
    int hh = h0 - 1 + r;
    float4 v = make_float4(0.f,0.f,0.f,0.f);
    if (hh >= 0 && hh < HH) v = *(const float4*)(xpc + (long)hh*WW + (tid<<2));
    *(float4*)(s + r*512 + (tid<<2)) = v;
  }
  __syncthreads();

  const float k0=wdw[c*9+0], k1=wdw[c*9+1], k2=wdw[c*9+2],
              k3=wdw[c*9+3], k4=wdw[c*9+4], k5=wdw[c*9+5],
              k6=wdw[c*9+6], k7=wdw[c*9+7], k8=wdw[c*9+8];
  const float rs = rsqrtf(1.0f+BN_EPS);
  const float sc = gcv[c]*rs, be = bcv[c];
  const int w = tid<<2;
  float* dst = g_xc + (long)(b*CH+c)*LL + (long)h0*WW + w;

  for (int r=0;r<16;r++){
    float in[3][6];
    #pragma unroll
    for (int dy=0;dy<3;dy++){
      const float* row = s + (r+dy)*512;
      in[dy][0] = (w>0)? row[w-1] : 0.f;
      float4 m = *(const float4*)(row + w);
      in[dy][1]=m.x; in[dy][2]=m.y; in[dy][3]=m.z; in[dy][4]=m.w;
      in[dy][5] = (w<508)? row[w+4] : 0.f;
    }
    float o[4];
    #pragma unroll
    for (int j=0;j<4;j++){
      float a = k0*in[0][j] + k1*in[0][j+1] + k2*in[0][j+2]
              + k3*in[1][j] + k4*in[1][j+1] + k5*in[1][j+2]
              + k6*in[2][j] + k7*in[2][j+1] + k8*in[2][j+2];
      a = fmaf(a, sc, be);
      o[j] = a*fsig(a);
    }
    *(float4*)(dst + (long)r*WW) = make_float4(o[0],o[1],o[2],o[3]);
  }
}

// ---------------------------------------------------------------------------
// K3a: Bp[s,k] = wB @ xc for k < CUT only (terms beyond are exactly 0 in fp32)
// ---------------------------------------------------------------------------
__global__ __launch_bounds__(128) void k_bproj(const float* __restrict__ wB)
{
  const int b = blockIdx.y;
  const int k = blockIdx.x*128 + threadIdx.x;
  const float* xcb = g_xc + (long)b*CH*LL + k;
  float acc[16];
  #pragma unroll
  for (int s=0;s<16;s++) acc[s]=0.f;
  for (int i=0;i<64;i++){
    float xv = xcb[(long)i*LL];
    #pragma unroll
    for (int s=0;s<16;s++) acc[s] = fmaf(__ldg(&wB[s*64+i]), xv, acc[s]);
  }
  #pragma unroll
  for (int s=0;s<16;s++) g_Bp[(b*DSTATE+s)*CUT + k] = acc[s];
}

// ---------------------------------------------------------------------------
// K3b: sequential inclusive cumsum of Bp[k]*exp(A*k) over k<CUT, per (b,s)
// ---------------------------------------------------------------------------
__global__ __launch_bounds__(256) void k_scan(const float* __restrict__ A)
{
  __shared__ float t[CUT];
  const int bs = blockIdx.x;       // b*16+s
  const int s = bs & 15;
  const float a = A[s];
  for (int idx = threadIdx.x; idx < CUT; idx += 256)
    t[idx] = g_Bp[bs*CUT + idx] * expf(a * (float)idx);
  __syncthreads();
  if (threadIdx.x == 0){
    float acc = 0.f;
    for (int k=0;k<CUT;k++){ acc += t[k]; t[k] = acc; }
    g_S[bs] = acc;
  }
  __syncthreads();
  for (int idx = threadIdx.x; idx < CUT; idx += 256)
    g_Sp[bs*CUT + idx] = t[idx];
}

// K3c: c[b,i] = wC[i,:] @ S[b,:]
__global__ void k_cproj(const float* __restrict__ wC)
{
  int idx = threadIdx.x;
  if (idx < BATCH*CH){
    int b = idx >> 6, i = idx & 63;
    float c = 0.f;
    #pragma unroll
    for (int s=0;s<16;s++) c = fmaf(wC[i*16+s], g_S[b*16+s], c);
    g_cv[idx] = c;
  }
}

// ---------------------------------------------------------------------------
// K4: fused gate GEMM (128x64) + SSM combine + out GEMM (64x64) + BN
// 128 pixels/block, 256 threads, 2 blocks/SM.  f32x2 packed FMAs.
// ---------------------------------------------------------------------------
__global__ __launch_bounds__(256,2) void k_final(
  const float* __restrict__ wC, const float* __restrict__ Dv,
  const float* __restrict__ wg, const float* __restrict__ gg, const float* __restrict__ bg,
  const float* __restrict__ wo, const float* __restrict__ go, const float* __restrict__ bo,
  float* __restrict__ out)
{
  extern __shared__ float sm[];
  float* Wg   = sm;              // [64][132] transposed gate weights
  float* buf1 = Wg + 64*132;     // xp tile, later xg tile
  float* buf2 = buf1 + 64*132;   // xc tile, later duplicated out weights
  __shared__ float cvec[64], dvec[64], gsc[128], gbe[128], osc[64], obe[64];

  const int tid = threadIdx.x;
  const int b = blockIdx.y;
  const long p0 = (long)blockIdx.x * 128;
  const bool boundary = (p0 < CUT);
  const float rs = rsqrtf(1.0f + BN_EPS);

  for (int idx = tid; idx < 128*64; idx += 256){
    int j = idx >> 6, i = idx & 63;
    Wg[i*132 + j] = wg[idx];
  }
  const float* xpb = g_xp + (long)b*CH*LL + p0;
  const float* xcb = g_xc + (long)b*CH*LL + p0;
  for (int idx = tid; idx < 64*32; idx += 256){
    int row = idx >> 5, c4 = idx & 31;
    *(float4*)(buf1 + row*132 + (c4<<2)) = *(const float4*)(xpb + (long)row*LL + (c4<<2));
    *(float4*)(buf2 + row*132 + (c4<<2)) = *(const float4*)(xcb + (long)row*LL + (c4<<2));
  }
  if (tid < 128){ gsc[tid] = gg[tid]*rs; gbe[tid] = bg[tid]; }
  else if (tid < 192){
    int o = tid - 128;
    cvec[o] = g_cv[b*64+o];
    dvec[o] = Dv[o];
    osc[o]  = go[o]*rs;
    obe[o]  = bo[o];
  }
  __syncthreads();

  const int og = tid >> 5, pg = tid & 31;

  // gate GEMM: output-pair packing, x broadcast {x,x}
  u64 ag2[4][4], as2[4][4];
  #pragma unroll
  for (int q2=0;q2<4;q2++)
    #pragma unroll
    for (int pp=0;pp<4;pp++){ ag2[q2][pp]=0ull; as2[q2][pp]=0ull; }

  #pragma unroll 4
  for (int i=0;i<64;i++){
    float4 xv = *(float4*)(buf1 + i*132 + (pg<<2));
    u64 xx[4];
    xx[0] = fpack2(xv.x, xv.x);
    xx[1] = fpack2(xv.y, xv.y);
    xx[2] = fpack2(xv.z, xv.z);
    xx[3] = fpack2(xv.w, xv.w);
    const u64* gp = (const u64*)(Wg + i*132 + (og<<3));
    const u64* sp = (const u64*)(Wg + i*132 + 64 + (og<<3));
    #pragma unroll
    for (int q2=0;q2<4;q2++){
      u64 wgv = gp[q2], wsv = sp[q2];
      #pragma unroll
      for (int pp=0;pp<4;pp++){
        ag2[q2][pp] = ffma2(wgv, xx[pp], ag2[q2][pp]);
        as2[q2][pp] = ffma2(wsv, xx[pp], as2[q2][pp]);
      }
    }
  }

  // combine: xg = sigmoid(bn(gate)) * (wC@state + D*xc + tanh(bn(shift)))
  float xg[8][4];
  #pragma unroll
  for (int q2=0;q2<4;q2++){
    const int i0 = (og<<3) + 2*q2;
    const int i1 = i0 + 1;
    float4 xc0 = *(float4*)(buf2 + i0*132 + (pg<<2));
    float4 xc1 = *(float4*)(buf2 + i1*132 + (pg<<2));
    float xca0[4] = {xc0.x,xc0.y,xc0.z,xc0.w};
    float xca1[4] = {xc1.x,xc1.y,xc1.z,xc1.w};
    float base0[4], base1[4];
    if (!boundary){
      float c0 = cvec[i0], c1 = cvec[i1];
      #pragma unroll
      for (int pp=0;pp<4;pp++){ base0[pp]=c0; base1[pp]=c1; }
    } else {
      #pragma unroll
      for (int pp=0;pp<4;pp++){
        long p = p0 + (pg<<2) + pp;
        float d0 = 0.f, d1 = 0.f;
        #pragma unroll
        for (int s=0;s<16;s++){
          float sv = g_Sp[(b*DSTATE+s)*CUT + p];
          d0 = fmaf(wC[i0*16+s], sv, d0);
          d1 = fmaf(wC[i1*16+s], sv, d1);
        }
        base0[pp]=d0; base1[pp]=d1;
      }
    }
    const float gs0=gsc[i0], gb0=gbe[i0], gs1=gsc[i1], gb1=gbe[i1];
    const float ss0=gsc[i0+64], sb0=gbe[i0+64], ss1=gsc[i1+64], sb1=gbe[i1+64];
    const float dv0=dvec[i0], dv1=dvec[i1];
    #pragma unroll
    for (int pp=0;pp<4;pp++){
      float g0,g1,s0,s1;
      funpack2(ag2[q2][pp], g0, g1);
      funpack2(as2[q2][pp], s0, s1);
      float gv0 = fmaf(g0, gs0, gb0);
      float gv1 = fmaf(g1, gs1, gb1);
      float sv0 = fmaf(s0, ss0, sb0);
      float sv1 = fmaf(s1, ss1, sb1);
      float ssm0 = fmaf(dv0, xca0[pp], base0[pp]);
      float ssm1 = fmaf(dv1, xca1[pp], base1[pp]);
      xg[2*q2  ][pp] = fsig(gv0) * (ssm0 + tanhf(sv0));
      xg[2*q2+1][pp] = fsig(gv1) * (ssm1 + tanhf(sv1));
    }
  }
  __syncthreads();

  // stage xg and duplicated out-proj weights
  #pragma unroll
  for (int q=0;q<8;q++){
    int i = (og<<3)+q;
    *(float4*)(buf1 + i*132 + (pg<<2)) = make_float4(xg[q][0],xg[q][1],xg[q][2],xg[q][3]);
  }
  for (int idx = tid; idx < 64*64; idx += 256){
    int o = idx >> 6, i = idx & 63;
    float v = wo[idx];
    buf2[i*132 + 2*o]     = v;
    buf2[i*132 + 2*o + 1] = v;
  }
  __syncthreads();

  // out GEMM: pixel-pair packing with duplicated weights
  u64 acc[8][2];
  #pragma unroll
  for (int q=0;q<8;q++){ acc[q][0]=0ull; acc[q][1]=0ull; }
  #pragma unroll 8
  for (int i=0;i<64;i++){
    const u64* xp2 = (const u64*)(buf1 + i*132 + (pg<<2));
    u64 x01 = xp2[0], x23 = xp2[1];
    const u64* wp2 = (const u64*)(buf2 + i*132 + (og<<4));
    #pragma unroll
    for (int q=0;q<8;q++){
      u64 w = wp2[q];
      acc[q][0] = ffma2(w, x01, acc[q][0]);
      acc[q][1] = ffma2(w, x23, acc[q][1]);
    }
  }

  #pragma unroll
  for (int q=0;q<8;q++){
    int o = (og<<3)+q;
    float sc = osc[o], be = obe[o];
    float v0,v1,v2,v3;
    funpack2(acc[q][0], v0, v1);
    funpack2(acc[q][1], v2, v3);
    float4 r = make_float4(fmaf(v0,sc,be), fmaf(v1,sc,be),
                           fmaf(v2,sc,be), fmaf(v3,sc,be));
    *(float4*)(out + (long)(b*CH+o)*LL + p0 + (pg<<2)) = r;
  }
}

// ---------------------------------------------------------------------------
extern "C" void kernel_launch(void* const* d_in, const int* in_sizes, int n_in,
                              void* d_out, int out_size)
{
  const float* x    = (const float*)d_in[0];
  const float* w_in = (const float*)d_in[1];
  const float* gin  = (const float*)d_in[2];
  const float* bin  = (const float*)d_in[3];
  const float* wdw  = (const float*)d_in[4];
  const float* gcv  = (const float*)d_in[5];
  const float* bcv  = (const float*)d_in[6];
  const float* wB   = (const float*)d_in[7];
  const float* wC   = (const float*)d_in[8];
  const float* A    = (const float*)d_in[9];
  const float* Dv   = (const float*)d_in[10];
  const float* wg   = (const float*)d_in[11];
  const float* gg   = (const float*)d_in[12];
  const float* bg   = (const float*)d_in[13];
  const float* wo   = (const float*)d_in[14];
  const float* go   = (const float*)d_in[15];
  const float* bo   = (const float*)d_in[16];
  float* out = (float*)d_out;

  const int SM1 = (2*64*132)*4;   // 67584 B
  const int SM4 = (3*64*132)*4;   // 101376 B
  cudaFuncSetAttribute(k_inproj, cudaFuncAttributeMaxDynamicSharedMemorySize, SM1);
  cudaFuncSetAttribute(k_final,  cudaFuncAttributeMaxDynamicSharedMemorySize, SM4);

  k_inproj<<<dim3(LL/128, BATCH), 256, SM1>>>(x, w_in, gin, bin);
  k_dwconv<<<dim3(HH/16, CH, BATCH), 128>>>(wdw, gcv, bcv);
  k_bproj <<<dim3(CUT/128, BATCH), 128>>>(wB);
  k_scan  <<<BATCH*DSTATE, 256>>>(A);
  k_cproj <<<1, 512>>>(wC);
  k_final <<<dim3(LL/128, BATCH), 256, SM4>>>(wC, Dv, wg, gg, bg, wo, go, bo, out);
}

// round 4
// speedup vs baseline: 1.3178x; 1.3178x over previous
#include <cuda_runtime.h>
#include <cuda_bf16.h>
#include <math.h>
#include <stdint.h>

#define BATCH 8
#define CH 64
#define HH 512
#define WW 512
#define LL (HH*WW)
#define DSTATE 16
#define CUT 2048
#define BN_EPS 1e-5f

// scratch
__device__ float g_xp[(size_t)BATCH*CH*LL];
__device__ float g_xc[(size_t)BATCH*CH*LL];
__device__ float g_Bp[BATCH*DSTATE*CUT];
__device__ float g_Sp[BATCH*DSTATE*CUT];
__device__ float g_S [BATCH*DSTATE];
__device__ float g_cv[BATCH*CH];

__device__ __forceinline__ float fsig(float x){ return 1.0f/(1.0f+__expf(-x)); }
__device__ __forceinline__ float ftanh(float x){
  x = fminf(fmaxf(x, -15.f), 15.f);
  float e = __expf(2.f*x);
  return __fdividef(e-1.f, e+1.f);
}

#define SW128(o) ((o) ^ (((o)>>3)&0x70))

__device__ __forceinline__ uint32_t smem_u32(const void* p){
  uint32_t a;
  asm("{ .reg .u64 t; cvta.to.shared.u64 t, %1; cvt.u32.u64 %0, t; }"
      : "=r"(a) : "l"(p));
  return a;
}
__device__ __forceinline__ void ldsm4(unsigned r[4], uint32_t a){
  asm volatile("ldmatrix.sync.aligned.m8n8.x4.shared.b16 {%0,%1,%2,%3}, [%4];"
    : "=r"(r[0]),"=r"(r[1]),"=r"(r[2]),"=r"(r[3]) : "r"(a));
}
__device__ __forceinline__ void ldsm2(unsigned r[2], uint32_t a){
  asm volatile("ldmatrix.sync.aligned.m8n8.x2.shared.b16 {%0,%1}, [%2];"
    : "=r"(r[0]),"=r"(r[1]) : "r"(a));
}
__device__ __forceinline__ void mma16816(float d[4], const unsigned a[4], const unsigned b[2]){
  asm volatile("mma.sync.aligned.m16n8k16.row.col.f32.bf16.bf16.f32 "
    "{%0,%1,%2,%3}, {%4,%5,%6,%7}, {%8,%9}, {%0,%1,%2,%3};"
    : "+f"(d[0]),"+f"(d[1]),"+f"(d[2]),"+f"(d[3])
    : "r"(a[0]),"r"(a[1]),"r"(a[2]),"r"(a[3]), "r"(b[0]),"r"(b[1]));
}

// split fp32 pair -> packed bf16 hi pair, lo pair (lo = residual)
__device__ __forceinline__ void split2(float v0, float v1, unsigned& hi, unsigned& lo){
  float h0 = __bfloat162float(__float2bfloat16_rn(v0));
  float h1 = __bfloat162float(__float2bfloat16_rn(v1));
  __nv_bfloat162 hp = __floats2bfloat162_rn(h0, h1);
  __nv_bfloat162 lp = __floats2bfloat162_rn(v0 - h0, v1 - h1);
  hi = *(unsigned*)&hp; lo = *(unsigned*)&lp;
}

// ---------------------------------------------------------------------------
// K1: xp = silu(bn(w_in @ x)) — mma.sync bf16-split. 256 px/block, 256 thr.
// ---------------------------------------------------------------------------
__global__ __launch_bounds__(256,2) void k_inproj(
    const float* __restrict__ x, const float* __restrict__ w_in,
    const float* __restrict__ gin, const float* __restrict__ bin)
{
  extern __shared__ char dynraw[];
  char* base = (char*)(((uintptr_t)dynraw + 1023) & ~(uintptr_t)1023);
  char* Ahi = base;            // 32KB: 256 rows x 128B
  char* Alo = base + 32768;    // 32KB
  char* Whi = base + 65536;    // 8KB: 64 rows x 128B
  char* Wlo = base + 73728;    // 8KB
  __shared__ float sg[64], sb[64];

  const int tid = threadIdx.x, lane = tid&31, warp = tid>>5;
  const int b = blockIdx.y;
  const long p0 = (long)blockIdx.x*256;

  for (int idx=tid; idx<4096; idx+=256){
    int n = idx>>6, k = idx&63;
    float v = w_in[idx];
    float h = __bfloat162float(__float2bfloat16_rn(v));
    unsigned off = SW128((unsigned)(n*128 + k*2));
    *(__nv_bfloat16*)(Whi+off) = __float2bfloat16_rn(v);
    *(__nv_bfloat16*)(Wlo+off) = __float2bfloat16_rn(v-h);
  }
  if (tid<64){ sg[tid]=gin[tid]*rsqrtf(1.f+BN_EPS); sb[tid]=bin[tid]; }

  { // A staging: thread = pixel
    const float* xb = x + (long)b*CH*LL + p0 + tid;
    unsigned hi[32], lo[32];
    #pragma unroll
    for (int c=0;c<32;c++) split2(xb[(long)(2*c)*LL], xb[(long)(2*c+1)*LL], hi[c], lo[c]);
    #pragma unroll
    for (int kb=0;kb<8;kb++){
      unsigned off = SW128((unsigned)(tid*128 + kb*16));
      *(uint4*)(Ahi+off) = make_uint4(hi[4*kb],hi[4*kb+1],hi[4*kb+2],hi[4*kb+3]);
      *(uint4*)(Alo+off) = make_uint4(lo[4*kb],lo[4*kb+1],lo[4*kb+2],lo[4*kb+3]);
    }
  }
  __syncthreads();

  const uint32_t AhiB=smem_u32(Ahi), AloB=smem_u32(Alo),
                 WhiB=smem_u32(Whi), WloB=smem_u32(Wlo);
  float acc[2][8][4];
  #pragma unroll
  for (int mt=0;mt<2;mt++)
    #pragma unroll
    for (int nt=0;nt<8;nt++)
      #pragma unroll
      for (int r=0;r<4;r++) acc[mt][nt][r]=0.f;

  const int Mb = warp*32;
  const int arow = (lane&7) + ((lane>>3)&1)*8;
  const int achk = lane>>4;
  const int brow = lane&7;
  const int bchk = (lane>>3)&1;

  #pragma unroll
  for (int ks=0; ks<4; ks++){
    unsigned ah[2][4], al[2][4];
    #pragma unroll
    for (int mt=0; mt<2; mt++){
      unsigned off = SW128((unsigned)((Mb+16*mt+arow)*128 + (2*ks+achk)*16));
      ldsm4(ah[mt], AhiB+off);
      ldsm4(al[mt], AloB+off);
    }
    #pragma unroll
    for (int nt=0; nt<8; nt++){
      unsigned boff = SW128((unsigned)((8*nt+brow)*128 + (2*ks+bchk)*16));
      unsigned bh[2], bl[2];
      ldsm2(bh, WhiB+boff);
      ldsm2(bl, WloB+boff);
      #pragma unroll
      for (int mt=0;mt<2;mt++){
        mma16816(acc[mt][nt], ah[mt], bh);
        mma16816(acc[mt][nt], al[mt], bh);
        mma16816(acc[mt][nt], ah[mt], bl);
      }
    }
  }
  __syncthreads();

  float* so = (float*)base;   // [64][268]
  #pragma unroll
  for (int mt=0;mt<2;mt++){
    int m = Mb + 16*mt + (lane>>2);
    #pragma unroll
    for (int nt=0;nt<8;nt++){
      int n = 8*nt + 2*(lane&3);
      so[n*268 + m]        = acc[mt][nt][0];
      so[(n+1)*268 + m]    = acc[mt][nt][1];
      so[n*268 + m + 8]    = acc[mt][nt][2];
      so[(n+1)*268 + m + 8]= acc[mt][nt][3];
    }
  }
  __syncthreads();

  float* dst = g_xp + (long)b*CH*LL + p0;
  #pragma unroll
  for (int r=0;r<16;r++){
    int f4 = tid + r*256;
    int ch = f4>>6, px = (f4&63)<<2;
    float4 v = *(float4*)(so + ch*268 + px);
    float sc = sg[ch], be = sb[ch];
    v.x = fmaf(v.x,sc,be); v.y = fmaf(v.y,sc,be);
    v.z = fmaf(v.z,sc,be); v.w = fmaf(v.w,sc,be);
    float4 o = make_float4(v.x*fsig(v.x), v.y*fsig(v.y), v.z*fsig(v.z), v.w*fsig(v.w));
    *(float4*)(dst + (long)ch*LL + px) = o;
  }
}

// ---------------------------------------------------------------------------
// K2: depthwise 3x3 + BN + SiLU (mem-bound, unchanged)
// ---------------------------------------------------------------------------
__global__ __launch_bounds__(128) void k_dwconv(
    const float* __restrict__ wdw, const float* __restrict__ gcv,
    const float* __restrict__ bcv)
{
  __shared__ float s[18*512];
  const int tid = threadIdx.x;
  const int b = blockIdx.z, c = blockIdx.y, h0 = blockIdx.x*16;
  const float* xpc = g_xp + (long)(b*CH+c)*LL;

  #pragma unroll
  for (int r=0;r<18;r++){
    int hh = h0 - 1 + r;
    float4 v = make_float4(0.f,0.f,0.f,0.f);
    if (hh >= 0 && hh < HH) v = *(const float4*)(xpc + (long)hh*WW + (tid<<2));
    *(float4*)(s + r*512 + (tid<<2)) = v;
  }
  __syncthreads();

  const float k0=wdw[c*9+0], k1=wdw[c*9+1], k2=wdw[c*9+2],
              k3=wdw[c*9+3], k4=wdw[c*9+4], k5=wdw[c*9+5],
              k6=wdw[c*9+6], k7=wdw[c*9+7], k8=wdw[c*9+8];
  const float rs = rsqrtf(1.0f+BN_EPS);
  const float sc = gcv[c]*rs, be = bcv[c];
  const int w = tid<<2;
  float* dst = g_xc + (long)(b*CH+c)*LL + (long)h0*WW + w;

  for (int r=0;r<16;r++){
    float in[3][6];
    #pragma unroll
    for (int dy=0;dy<3;dy++){
      const float* row = s + (r+dy)*512;
      in[dy][0] = (w>0)? row[w-1] : 0.f;
      float4 m = *(const float4*)(row + w);
      in[dy][1]=m.x; in[dy][2]=m.y; in[dy][3]=m.z; in[dy][4]=m.w;
      in[dy][5] = (w<508)? row[w+4] : 0.f;
    }
    float o[4];
    #pragma unroll
    for (int j=0;j<4;j++){
      float a = k0*in[0][j] + k1*in[0][j+1] + k2*in[0][j+2]
              + k3*in[1][j] + k4*in[1][j+1] + k5*in[1][j+2]
              + k6*in[2][j] + k7*in[2][j+1] + k8*in[2][j+2];
      a = fmaf(a, sc, be);
      o[j] = a*fsig(a);
    }
    *(float4*)(dst + (long)r*WW) = make_float4(o[0],o[1],o[2],o[3]);
  }
}

// ---------------------------------------------------------------------------
// K3: SSM pieces (tiny)
// ---------------------------------------------------------------------------
__global__ __launch_bounds__(128) void k_bproj(const float* __restrict__ wB)
{
  const int b = blockIdx.y;
  const int k = blockIdx.x*128 + threadIdx.x;
  const float* xcb = g_xc + (long)b*CH*LL + k;
  float acc[16];
  #pragma unroll
  for (int s=0;s<16;s++) acc[s]=0.f;
  for (int i=0;i<64;i++){
    float xv = xcb[(long)i*LL];
    #pragma unroll
    for (int s=0;s<16;s++) acc[s] = fmaf(__ldg(&wB[s*64+i]), xv, acc[s]);
  }
  #pragma unroll
  for (int s=0;s<16;s++) g_Bp[(b*DSTATE+s)*CUT + k] = acc[s];
}

__global__ __launch_bounds__(256) void k_scan(const float* __restrict__ A)
{
  __shared__ float t[CUT];
  const int bs = blockIdx.x;
  const int s = bs & 15;
  const float a = A[s];
  for (int idx = threadIdx.x; idx < CUT; idx += 256)
    t[idx] = g_Bp[bs*CUT + idx] * expf(a * (float)idx);
  __syncthreads();
  if (threadIdx.x == 0){
    float acc = 0.f;
    for (int k=0;k<CUT;k++){ acc += t[k]; t[k] = acc; }
    g_S[bs] = acc;
  }
  __syncthreads();
  for (int idx = threadIdx.x; idx < CUT; idx += 256)
    g_Sp[bs*CUT + idx] = t[idx];
}

__global__ void k_cproj(const float* __restrict__ wC)
{
  int idx = threadIdx.x;
  if (idx < BATCH*CH){
    int b = idx >> 6, i = idx & 63;
    float c = 0.f;
    #pragma unroll
    for (int s=0;s<16;s++) c = fmaf(wC[i*16+s], g_S[b*16+s], c);
    g_cv[idx] = c;
  }
}

// ---------------------------------------------------------------------------
// K4: gate GEMM (N=128) + combine + out GEMM (N=64), mma.sync bf16-split.
// 128 px/block, 256 thr (8 warps, 1 m-tile each).
// ---------------------------------------------------------------------------
__global__ __launch_bounds__(256,2) void k_final(
  const float* __restrict__ wC, const float* __restrict__ Dv,
  const float* __restrict__ wg, const float* __restrict__ gg, const float* __restrict__ bg,
  const float* __restrict__ wo, const float* __restrict__ go, const float* __restrict__ bo,
  float* __restrict__ out)
{
  extern __shared__ char dynraw[];
  char* base = (char*)(((uintptr_t)dynraw + 1023) & ~(uintptr_t)1023);
  char* Ahi  = base;            // 16KB: 128 rows x 128B (xp, later xg)
  char* Alo  = base + 16384;    // 16KB
  char* WgHi = base + 32768;    // 16KB: 128 rows
  char* WgLo = base + 49152;    // 16KB
  char* WoHi = base + 65536;    // 8KB
  char* WoLo = base + 73728;    // 8KB
  __shared__ float s_gsc[128], s_gbe[128], s_dvec[64], s_cvec[64], s_osc[64], s_obe[64];
  __shared__ float s_wC[64*16];

  const int tid = threadIdx.x, lane = tid&31, warp = tid>>5;
  const int b = blockIdx.y;
  const long p0 = (long)blockIdx.x*128;
  const bool boundary = (p0 < CUT);
  const float rs = rsqrtf(1.0f+BN_EPS);

  for (int idx=tid; idx<8192; idx+=256){
    int n = idx>>6, k = idx&63;
    float v = wg[idx];
    float h = __bfloat162float(__float2bfloat16_rn(v));
    unsigned off = SW128((unsigned)(n*128 + k*2));
    *(__nv_bfloat16*)(WgHi+off) = __float2bfloat16_rn(v);
    *(__nv_bfloat16*)(WgLo+off) = __float2bfloat16_rn(v-h);
  }
  for (int idx=tid; idx<4096; idx+=256){
    int n = idx>>6, k = idx&63;
    float v = wo[idx];
    float h = __bfloat162float(__float2bfloat16_rn(v));
    unsigned off = SW128((unsigned)(n*128 + k*2));
    *(__nv_bfloat16*)(WoHi+off) = __float2bfloat16_rn(v);
    *(__nv_bfloat16*)(WoLo+off) = __float2bfloat16_rn(v-h);
  }
  if (tid < 128){ s_gsc[tid] = gg[tid]*rs; s_gbe[tid] = bg[tid]; }
  if (tid < 64){
    s_dvec[tid] = Dv[tid];
    s_cvec[tid] = g_cv[b*64+tid];
    s_osc[tid]  = go[tid]*rs;
    s_obe[tid]  = bo[tid];
  }
  if (boundary)
    for (int idx=tid; idx<1024; idx+=256) s_wC[idx] = wC[idx];

  { // A staging: thread = (px = tid&127, channel half = tid>>7)
    const int px = tid & 127, half = tid >> 7;
    const float* xpb = g_xp + (long)b*CH*LL + (long)(half*32)*LL + p0 + px;
    unsigned hi[16], lo[16];
    #pragma unroll
    for (int c=0;c<16;c++) split2(xpb[(long)(2*c)*LL], xpb[(long)(2*c+1)*LL], hi[c], lo[c]);
    #pragma unroll
    for (int j=0;j<4;j++){
      unsigned off = SW128((unsigned)(px*128 + (half*4+j)*16));
      *(uint4*)(Ahi+off) = make_uint4(hi[4*j],hi[4*j+1],hi[4*j+2],hi[4*j+3]);
      *(uint4*)(Alo+off) = make_uint4(lo[4*j],lo[4*j+1],lo[4*j+2],lo[4*j+3]);
    }
  }
  __syncthreads();

  const uint32_t AhiB=smem_u32(Ahi), AloB=smem_u32(Alo),
                 WgHiB=smem_u32(WgHi), WgLoB=smem_u32(WgLo),
                 WoHiB=smem_u32(WoHi), WoLoB=smem_u32(WoLo);
  const int Mb = warp*16;
  const int arow = (lane&7) + ((lane>>3)&1)*8;
  const int achk = lane>>4;
  const int brow = lane&7;
  const int bchk = (lane>>3)&1;

  // gate GEMM: 16 n-tiles
  float acc[16][4];
  #pragma unroll
  for (int nt=0;nt<16;nt++)
    #pragma unroll
    for (int r=0;r<4;r++) acc[nt][r]=0.f;

  #pragma unroll
  for (int ks=0; ks<4; ks++){
    unsigned ah[4], al[4];
    unsigned aoff = SW128((unsigned)((Mb+arow)*128 + (2*ks+achk)*16));
    ldsm4(ah, AhiB+aoff);
    ldsm4(al, AloB+aoff);
    #pragma unroll
    for (int nt=0; nt<16; nt++){
      unsigned boff = SW128((unsigned)((8*nt+brow)*128 + (2*ks+bchk)*16));
      unsigned bh[2], bl[2];
      ldsm2(bh, WgHiB+boff);
      ldsm2(bl, WgLoB+boff);
      mma16816(acc[nt], ah, bh);
      mma16816(acc[nt], al, bh);
      mma16816(acc[nt], ah, bl);
    }
  }
  __syncthreads();   // all warps done reading Ahi/Alo before xg overwrite

  // combine -> xg, split, stage into Ahi/Alo
  float sp0[16], sp1[16];
  if (boundary){
    const long pA = p0 + Mb + (lane>>2);
    #pragma unroll
    for (int s=0;s<16;s++){
      sp0[s] = g_Sp[(b*DSTATE+s)*CUT + pA];
      sp1[s] = g_Sp[(b*DSTATE+s)*CUT + pA + 8];
    }
  }
  {
    const float* xcb = g_xc + (long)b*CH*LL + p0;
    #pragma unroll
    for (int nt=0; nt<8; nt++){
      const int ch0 = 8*nt + 2*(lane&3), ch1 = ch0+1;
      #pragma unroll
      for (int rp=0; rp<2; rp++){
        const int pxl = Mb + (lane>>2) + rp*8;
        float base0, base1;
        if (boundary){
          const float* sp = rp ? sp1 : sp0;
          float d0=0.f, d1=0.f;
          #pragma unroll
          for (int s=0;s<16;s++){
            d0 = fmaf(s_wC[ch0*16+s], sp[s], d0);
            d1 = fmaf(s_wC[ch1*16+s], sp[s], d1);
          }
          base0=d0; base1=d1;
        } else { base0 = s_cvec[ch0]; base1 = s_cvec[ch1]; }
        float xc0 = xcb[(long)ch0*LL + pxl];
        float xc1 = xcb[(long)ch1*LL + pxl];
        float g0 = fmaf(acc[nt][2*rp],   s_gsc[ch0], s_gbe[ch0]);
        float g1 = fmaf(acc[nt][2*rp+1], s_gsc[ch1], s_gbe[ch1]);
        float h0 = fmaf(acc[nt+8][2*rp],   s_gsc[64+ch0], s_gbe[64+ch0]);
        float h1 = fmaf(acc[nt+8][2*rp+1], s_gsc[64+ch1], s_gbe[64+ch1]);
        float v0 = fsig(g0)*(fmaf(s_dvec[ch0], xc0, base0) + ftanh(h0));
        float v1 = fsig(g1)*(fmaf(s_dvec[ch1], xc1, base1) + ftanh(h1));
        unsigned hi, lo;
        split2(v0, v1, hi, lo);
        unsigned off = SW128((unsigned)(pxl*128 + ch0*2));
        *(unsigned*)(Ahi+off) = hi;
        *(unsigned*)(Alo+off) = lo;
      }
    }
  }
  __syncthreads();

  // out GEMM: 8 n-tiles
  float acc2[8][4];
  #pragma unroll
  for (int nt=0;nt<8;nt++)
    #pragma unroll
    for (int r=0;r<4;r++) acc2[nt][r]=0.f;
  #pragma unroll
  for (int ks=0; ks<4; ks++){
    unsigned ah[4], al[4];
    unsigned aoff = SW128((unsigned)((Mb+arow)*128 + (2*ks+achk)*16));
    ldsm4(ah, AhiB+aoff);
    ldsm4(al, AloB+aoff);
    #pragma unroll
    for (int nt=0; nt<8; nt++){
      unsigned boff = SW128((unsigned)((8*nt+brow)*128 + (2*ks+bchk)*16));
      unsigned bh[2], bl[2];
      ldsm2(bh, WoHiB+boff);
      ldsm2(bl, WoLoB+boff);
      mma16816(acc2[nt], ah, bh);
      mma16816(acc2[nt], al, bh);
      mma16816(acc2[nt], ah, bl);
    }
  }
  __syncthreads();

  float* so = (float*)(base + 32768);   // [64][132]
  {
    int m = Mb + (lane>>2);
    #pragma unroll
    for (int nt=0;nt<8;nt++){
      int n = 8*nt + 2*(lane&3);
      so[n*132 + m]        = acc2[nt][0];
      so[(n+1)*132 + m]    = acc2[nt][1];
      so[n*132 + m + 8]    = acc2[nt][2];
      so[(n+1)*132 + m + 8]= acc2[nt][3];
    }
  }
  __syncthreads();

  float* dst = out + (long)b*CH*LL + p0;
  #pragma unroll
  for (int r=0;r<8;r++){
    int f4 = tid + r*256;
    int ch = f4>>5, px = (f4&31)<<2;
    float4 v = *(float4*)(so + ch*132 + px);
    float sc = s_osc[ch], be = s_obe[ch];
    float4 o = make_float4(fmaf(v.x,sc,be), fmaf(v.y,sc,be),
                           fmaf(v.z,sc,be), fmaf(v.w,sc,be));
    *(float4*)(dst + (long)ch*LL + px) = o;
  }
}

// ---------------------------------------------------------------------------
extern "C" void kernel_launch(void* const* d_in, const int* in_sizes, int n_in,
                              void* d_out, int out_size)
{
  const float* x    = (const float*)d_in[0];
  const float* w_in = (const float*)d_in[1];
  const float* gin  = (const float*)d_in[2];
  const float* bin  = (const float*)d_in[3];
  const float* wdw  = (const float*)d_in[4];
  const float* gcv  = (const float*)d_in[5];
  const float* bcv  = (const float*)d_in[6];
  const float* wB   = (const float*)d_in[7];
  const float* wC   = (const float*)d_in[8];
  const float* A    = (const float*)d_in[9];
  const float* Dv   = (const float*)d_in[10];
  const float* wg   = (const float*)d_in[11];
  const float* gg   = (const float*)d_in[12];
  const float* bg   = (const float*)d_in[13];
  const float* wo   = (const float*)d_in[14];
  const float* go   = (const float*)d_in[15];
  const float* bo   = (const float*)d_in[16];
  float* out = (float*)d_out;

  const int SM1 = 81920 + 1024;
  const int SM4 = 81920 + 1024;
  cudaFuncSetAttribute(k_inproj, cudaFuncAttributeMaxDynamicSharedMemorySize, SM1);
  cudaFuncSetAttribute(k_final,  cudaFuncAttributeMaxDynamicSharedMemorySize, SM4);

  k_inproj<<<dim3(LL/256, BATCH), 256, SM1>>>(x, w_in, gin, bin);
  k_dwconv<<<dim3(HH/16, CH, BATCH), 128>>>(wdw, gcv, bcv);
  k_bproj <<<dim3(CUT/128, BATCH), 128>>>(wB);
  k_scan  <<<BATCH*DSTATE, 256>>>(A);
  k_cproj <<<1, 512>>>(wC);
  k_final <<<dim3(LL/128, BATCH), 256, SM4>>>(wC, Dv, wg, gg, bg, wo, go, bo, out);
}

// round 5
// speedup vs baseline: 1.5414x; 1.1696x over previous
#include <cuda_runtime.h>
#include <cuda_bf16.h>
#include <math.h>
#include <stdint.h>

#define BATCH 8
#define CH 64
#define HH 512
#define WW 512
#define LL (HH*WW)
#define DSTATE 16
#define CUT 2048
#define BN_EPS 1e-5f

// scratch
__device__ float g_xp[(size_t)BATCH*CH*LL];
__device__ float g_xc[(size_t)BATCH*CH*LL];
__device__ float g_Bp[BATCH*DSTATE*CUT];
__device__ float g_Sp[BATCH*DSTATE*CUT];
__device__ float g_S [BATCH*DSTATE];
__device__ float g_cv[BATCH*CH];

// pre-swizzled bf16 hi/lo weight tiles
__device__ __align__(16) unsigned char g_WinH[8192],  g_WinL[8192];
__device__ __align__(16) unsigned char g_WgH[16384],  g_WgL[16384];
__device__ __align__(16) unsigned char g_WoH[8192],   g_WoL[8192];

__device__ __forceinline__ float fsig(float x){ return 1.0f/(1.0f+__expf(-x)); }
__device__ __forceinline__ float ftanh(float x){
  x = fminf(fmaxf(x, -15.f), 15.f);
  float e = __expf(2.f*x);
  return __fdividef(e-1.f, e+1.f);
}

#define SW128(o) ((o) ^ (((o)>>3)&0x70))

__device__ __forceinline__ uint32_t smem_u32(const void* p){
  uint32_t a;
  asm("{ .reg .u64 t; cvta.to.shared.u64 t, %1; cvt.u32.u64 %0, t; }"
      : "=r"(a) : "l"(p));
  return a;
}
__device__ __forceinline__ void ldsm4(unsigned r[4], uint32_t a){
  asm volatile("ldmatrix.sync.aligned.m8n8.x4.shared.b16 {%0,%1,%2,%3}, [%4];"
    : "=r"(r[0]),"=r"(r[1]),"=r"(r[2]),"=r"(r[3]) : "r"(a));
}
__device__ __forceinline__ void ldsm2(unsigned r[2], uint32_t a){
  asm volatile("ldmatrix.sync.aligned.m8n8.x2.shared.b16 {%0,%1}, [%2];"
    : "=r"(r[0]),"=r"(r[1]) : "r"(a));
}
__device__ __forceinline__ void mma16816(float d[4], const unsigned a[4], const unsigned b[2]){
  asm volatile("mma.sync.aligned.m16n8k16.row.col.f32.bf16.bf16.f32 "
    "{%0,%1,%2,%3}, {%4,%5,%6,%7}, {%8,%9}, {%0,%1,%2,%3};"
    : "+f"(d[0]),"+f"(d[1]),"+f"(d[2]),"+f"(d[3])
    : "r"(a[0]),"r"(a[1]),"r"(a[2]),"r"(a[3]), "r"(b[0]),"r"(b[1]));
}

// fast truncation split: hi = top-16-bit truncation (exact residual), lo = rn(residual)
__device__ __forceinline__ void split2t(float v0, float v1, unsigned& hi, unsigned& lo){
  unsigned u0 = __float_as_uint(v0), u1 = __float_as_uint(v1);
  unsigned h;
  asm("prmt.b32 %0, %1, %2, 0x7632;" : "=r"(h) : "r"(u0), "r"(u1));
  float r0 = v0 - __uint_as_float(u0 & 0xFFFF0000u);
  float r1 = v1 - __uint_as_float(u1 & 0xFFFF0000u);
  unsigned l;
  asm("cvt.rn.bf16x2.f32 %0, %1, %2;" : "=r"(l) : "f"(r1), "f"(r0));
  hi = h; lo = l;
}

// ---------------------------------------------------------------------------
// K0: one-time weight prep (bf16 hi/lo, SW128 swizzled rows of 128B)
// ---------------------------------------------------------------------------
__global__ void k_prep(const float* __restrict__ w_in,
                       const float* __restrict__ wg,
                       const float* __restrict__ wo)
{
  const int tid = threadIdx.x;
  for (int idx=tid; idx<4096; idx+=256){
    int n = idx>>6, k = idx&63;
    unsigned off = SW128((unsigned)(n*128 + k*2));
    { float v = w_in[idx];
      float h = __bfloat162float(__float2bfloat16_rn(v));
      *(__nv_bfloat16*)(g_WinH+off) = __float2bfloat16_rn(v);
      *(__nv_bfloat16*)(g_WinL+off) = __float2bfloat16_rn(v-h); }
    { float v = wo[idx];
      float h = __bfloat162float(__float2bfloat16_rn(v));
      *(__nv_bfloat16*)(g_WoH+off) = __float2bfloat16_rn(v);
      *(__nv_bfloat16*)(g_WoL+off) = __float2bfloat16_rn(v-h); }
  }
  for (int idx=tid; idx<8192; idx+=256){
    int n = idx>>6, k = idx&63;
    unsigned off = SW128((unsigned)(n*128 + k*2));
    float v = wg[idx];
    float h = __bfloat162float(__float2bfloat16_rn(v));
    *(__nv_bfloat16*)(g_WgH+off) = __float2bfloat16_rn(v);
    *(__nv_bfloat16*)(g_WgL+off) = __float2bfloat16_rn(v-h);
  }
}

// ---------------------------------------------------------------------------
// K1: xp = silu(bn(w_in @ x)) — mma.sync bf16-split. 256 px/block, 256 thr.
// ---------------------------------------------------------------------------
__global__ __launch_bounds__(256,2) void k_inproj(
    const float* __restrict__ x,
    const float* __restrict__ gin, const float* __restrict__ bin)
{
  extern __shared__ char dynraw[];
  char* base = (char*)(((uintptr_t)dynraw + 1023) & ~(uintptr_t)1023);
  char* Ahi = base;            // 32KB
  char* Alo = base + 32768;    // 32KB
  char* Whi = base + 65536;    // 8KB
  char* Wlo = base + 73728;    // 8KB
  __shared__ float sg[64], sb[64];

  const int tid = threadIdx.x, lane = tid&31, warp = tid>>5;
  const int b = blockIdx.y;
  const long p0 = (long)blockIdx.x*256;

  for (int idx=tid; idx<512; idx+=256){
    ((uint4*)Whi)[idx] = ((const uint4*)g_WinH)[idx];
    ((uint4*)Wlo)[idx] = ((const uint4*)g_WinL)[idx];
  }
  if (tid<64){ sg[tid]=gin[tid]*rsqrtf(1.f+BN_EPS); sb[tid]=bin[tid]; }

  { // A staging: thread = pixel
    const float* xb = x + (long)b*CH*LL + p0 + tid;
    #pragma unroll
    for (int kb=0;kb<8;kb++){
      unsigned h[4], l[4];
      #pragma unroll
      for (int j=0;j<4;j++)
        split2t(xb[(long)(8*kb+2*j)*LL], xb[(long)(8*kb+2*j+1)*LL], h[j], l[j]);
      unsigned off = SW128((unsigned)(tid*128 + kb*16));
      *(uint4*)(Ahi+off) = make_uint4(h[0],h[1],h[2],h[3]);
      *(uint4*)(Alo+off) = make_uint4(l[0],l[1],l[2],l[3]);
    }
  }
  __syncthreads();

  const uint32_t AhiB=smem_u32(Ahi), AloB=smem_u32(Alo),
                 WhiB=smem_u32(Whi), WloB=smem_u32(Wlo);
  float acc[2][8][4];
  #pragma unroll
  for (int mt=0;mt<2;mt++)
    #pragma unroll
    for (int nt=0;nt<8;nt++)
      #pragma unroll
      for (int r=0;r<4;r++) acc[mt][nt][r]=0.f;

  const int Mb = warp*32;
  const int arow = (lane&7) + ((lane>>3)&1)*8;
  const int achk = lane>>4;
  const int brow = lane&7;
  const int bchk = (lane>>3)&1;

  #pragma unroll
  for (int ks=0; ks<4; ks++){
    unsigned ah[2][4], al[2][4];
    #pragma unroll
    for (int mt=0; mt<2; mt++){
      unsigned off = SW128((unsigned)((Mb+16*mt+arow)*128 + (2*ks+achk)*16));
      ldsm4(ah[mt], AhiB+off);
      ldsm4(al[mt], AloB+off);
    }
    #pragma unroll
    for (int nt=0; nt<8; nt++){
      unsigned boff = SW128((unsigned)((8*nt+brow)*128 + (2*ks+bchk)*16));
      unsigned bh[2], bl[2];
      ldsm2(bh, WhiB+boff);
      ldsm2(bl, WloB+boff);
      #pragma unroll
      for (int mt=0;mt<2;mt++){
        mma16816(acc[mt][nt], ah[mt], bh);
        mma16816(acc[mt][nt], al[mt], bh);
        mma16816(acc[mt][nt], ah[mt], bl);
      }
    }
  }
  __syncthreads();

  float* so = (float*)base;   // [64][268] ~68.6KB (Ahi+Alo+part of Whi, all dead)
  #pragma unroll
  for (int mt=0;mt<2;mt++){
    int m = Mb + 16*mt + (lane>>2);
    #pragma unroll
    for (int nt=0;nt<8;nt++){
      int n = 8*nt + 2*(lane&3);
      so[n*268 + m]        = acc[mt][nt][0];
      so[(n+1)*268 + m]    = acc[mt][nt][1];
      so[n*268 + m + 8]    = acc[mt][nt][2];
      so[(n+1)*268 + m + 8]= acc[mt][nt][3];
    }
  }
  __syncthreads();

  float* dst = g_xp + (long)b*CH*LL + p0;
  #pragma unroll
  for (int r=0;r<16;r++){
    int f4 = tid + r*256;
    int ch = f4>>6, px = (f4&63)<<2;
    float4 v = *(float4*)(so + ch*268 + px);
    float sc = sg[ch], be = sb[ch];
    v.x = fmaf(v.x,sc,be); v.y = fmaf(v.y,sc,be);
    v.z = fmaf(v.z,sc,be); v.w = fmaf(v.w,sc,be);
    float4 o = make_float4(v.x*fsig(v.x), v.y*fsig(v.y), v.z*fsig(v.z), v.w*fsig(v.w));
    *(float4*)(dst + (long)ch*LL + px) = o;
  }
}

// ---------------------------------------------------------------------------
// K2: depthwise 3x3 + BN + SiLU (mem-bound)
// ---------------------------------------------------------------------------
__global__ __launch_bounds__(128) void k_dwconv(
    const float* __restrict__ wdw, const float* __restrict__ gcv,
    const float* __restrict__ bcv)
{
  __shared__ float s[18*512];
  const int tid = threadIdx.x;
  const int b = blockIdx.z, c = blockIdx.y, h0 = blockIdx.x*16;
  const float* xpc = g_xp + (long)(b*CH+c)*LL;

  #pragma unroll
  for (int r=0;r<18;r++){
    int hh = h0 - 1 + r;
    float4 v = make_float4(0.f,0.f,0.f,0.f);
    if (hh >= 0 && hh < HH) v = *(const float4*)(xpc + (long)hh*WW + (tid<<2));
    *(float4*)(s + r*512 + (tid<<2)) = v;
  }
  __syncthreads();

  const float k0=wdw[c*9+0], k1=wdw[c*9+1], k2=wdw[c*9+2],
              k3=wdw[c*9+3], k4=wdw[c*9+4], k5=wdw[c*9+5],
              k6=wdw[c*9+6], k7=wdw[c*9+7], k8=wdw[c*9+8];
  const float rs = rsqrtf(1.0f+BN_EPS);
  const float sc = gcv[c]*rs, be = bcv[c];
  const int w = tid<<2;
  float* dst = g_xc + (long)(b*CH+c)*LL + (long)h0*WW + w;

  for (int r=0;r<16;r++){
    float in[3][6];
    #pragma unroll
    for (int dy=0;dy<3;dy++){
      const float* row = s + (r+dy)*512;
      in[dy][0] = (w>0)? row[w-1] : 0.f;
      float4 m = *(const float4*)(row + w);
      in[dy][1]=m.x; in[dy][2]=m.y; in[dy][3]=m.z; in[dy][4]=m.w;
      in[dy][5] = (w<508)? row[w+4] : 0.f;
    }
    float o[4];
    #pragma unroll
    for (int j=0;j<4;j++){
      float a = k0*in[0][j] + k1*in[0][j+1] + k2*in[0][j+2]
              + k3*in[1][j] + k4*in[1][j+1] + k5*in[1][j+2]
              + k6*in[2][j] + k7*in[2][j+1] + k8*in[2][j+2];
      a = fmaf(a, sc, be);
      o[j] = a*fsig(a);
    }
    *(float4*)(dst + (long)r*WW) = make_float4(o[0],o[1],o[2],o[3]);
  }
}

// ---------------------------------------------------------------------------
// K3: SSM pieces (tiny)
// ---------------------------------------------------------------------------
__global__ __launch_bounds__(128) void k_bproj(const float* __restrict__ wB)
{
  const int b = blockIdx.y;
  const int k = blockIdx.x*128 + threadIdx.x;
  const float* xcb = g_xc + (long)b*CH*LL + k;
  float acc[16];
  #pragma unroll
  for (int s=0;s<16;s++) acc[s]=0.f;
  for (int i=0;i<64;i++){
    float xv = xcb[(long)i*LL];
    #pragma unroll
    for (int s=0;s<16;s++) acc[s] = fmaf(__ldg(&wB[s*64+i]), xv, acc[s]);
  }
  #pragma unroll
  for (int s=0;s<16;s++) g_Bp[(b*DSTATE+s)*CUT + k] = acc[s];
}

__global__ __launch_bounds__(256) void k_scan(const float* __restrict__ A)
{
  __shared__ float t[CUT];
  const int bs = blockIdx.x;
  const int s = bs & 15;
  const float a = A[s];
  for (int idx = threadIdx.x; idx < CUT; idx += 256)
    t[idx] = g_Bp[bs*CUT + idx] * expf(a * (float)idx);
  __syncthreads();
  if (threadIdx.x == 0){
    float acc = 0.f;
    for (int k=0;k<CUT;k++){ acc += t[k]; t[k] = acc; }
    g_S[bs] = acc;
  }
  __syncthreads();
  for (int idx = threadIdx.x; idx < CUT; idx += 256)
    g_Sp[bs*CUT + idx] = t[idx];
}

__global__ void k_cproj(const float* __restrict__ wC)
{
  int idx = threadIdx.x;
  if (idx < BATCH*CH){
    int b = idx >> 6, i = idx & 63;
    float c = 0.f;
    #pragma unroll
    for (int s=0;s<16;s++) c = fmaf(wC[i*16+s], g_S[b*16+s], c);
    g_cv[idx] = c;
  }
}

// ---------------------------------------------------------------------------
// K4: gate GEMM + combine + out GEMM, streaming per-nt (no register spills).
// 128 px/block, 256 thr (8 warps, m16 tile each), 2 blocks/SM.
// ---------------------------------------------------------------------------
__global__ __launch_bounds__(256,2) void k_final(
  const float* __restrict__ wC, const float* __restrict__ Dv,
  const float* __restrict__ gg, const float* __restrict__ bg,
  const float* __restrict__ go, const float* __restrict__ bo,
  float* __restrict__ out)
{
  extern __shared__ char dynraw[];
  char* base = (char*)(((uintptr_t)dynraw + 1023) & ~(uintptr_t)1023);
  char* Ahi  = base;            // 16KB (xp, later xg)
  char* Alo  = base + 16384;    // 16KB
  char* WgHi = base + 32768;    // 16KB
  char* WgLo = base + 49152;    // 16KB
  char* WoHi = base + 65536;    // 8KB
  char* WoLo = base + 73728;    // 8KB
  __shared__ float s_gsc[128], s_gbe[128], s_dvec[64], s_cvec[64], s_osc[64], s_obe[64];
  __shared__ float s_wC[64*16];

  const int tid = threadIdx.x, lane = tid&31, warp = tid>>5;
  const int b = blockIdx.y;
  const long p0 = (long)blockIdx.x*128;
  const bool boundary = (p0 < CUT);
  const float rs = rsqrtf(1.0f+BN_EPS);

  for (int idx=tid; idx<1024; idx+=256){
    ((uint4*)WgHi)[idx] = ((const uint4*)g_WgH)[idx];
    ((uint4*)WgLo)[idx] = ((const uint4*)g_WgL)[idx];
  }
  for (int idx=tid; idx<512; idx+=256){
    ((uint4*)WoHi)[idx] = ((const uint4*)g_WoH)[idx];
    ((uint4*)WoLo)[idx] = ((const uint4*)g_WoL)[idx];
  }
  if (tid < 128){ s_gsc[tid] = gg[tid]*rs; s_gbe[tid] = bg[tid]; }
  if (tid < 64){
    s_dvec[tid] = Dv[tid];
    s_cvec[tid] = g_cv[b*64+tid];
    s_osc[tid]  = go[tid]*rs;
    s_obe[tid]  = bo[tid];
  }
  if (boundary)
    for (int idx=tid; idx<1024; idx+=256) s_wC[idx] = wC[idx];

  { // A staging: thread = (px = tid&127, channel half = tid>>7)
    const int px = tid & 127, half = tid >> 7;
    const float* xpb = g_xp + (long)b*CH*LL + (long)(half*32)*LL + p0 + px;
    #pragma unroll
    for (int j=0;j<4;j++){
      unsigned h[4], l[4];
      #pragma unroll
      for (int c=0;c<4;c++)
        split2t(xpb[(long)(8*j+2*c)*LL], xpb[(long)(8*j+2*c+1)*LL], h[c], l[c]);
      unsigned off = SW128((unsigned)(px*128 + (half*4+j)*16));
      *(uint4*)(Ahi+off) = make_uint4(h[0],h[1],h[2],h[3]);
      *(uint4*)(Alo+off) = make_uint4(l[0],l[1],l[2],l[3]);
    }
  }
  __syncthreads();

  const uint32_t AhiB=smem_u32(Ahi), AloB=smem_u32(Alo),
                 WgHiB=smem_u32(WgHi), WgLoB=smem_u32(WgLo),
                 WoHiB=smem_u32(WoHi), WoLoB=smem_u32(WoLo);
  const int Mb = warp*16;
  const int arow = (lane&7) + ((lane>>3)&1)*8;
  const int achk = lane>>4;
  const int brow = lane&7;
  const int bchk = (lane>>3)&1;

  // preload A fragments (xp) once: 32 regs
  unsigned ah[4][4], al[4][4];
  #pragma unroll
  for (int ks=0; ks<4; ks++){
    unsigned aoff = SW128((unsigned)((Mb+arow)*128 + (2*ks+achk)*16));
    ldsm4(ah[ks], AhiB+aoff);
    ldsm4(al[ks], AloB+aoff);
  }

  // gate GEMM + combine, streamed per nt (gate ch 8nt..8nt+7, shift ch +64)
  const float* xcb = g_xc + (long)b*CH*LL + p0;
  #pragma unroll
  for (int nt=0; nt<8; nt++){
    float accg[4] = {0.f,0.f,0.f,0.f};
    float accs[4] = {0.f,0.f,0.f,0.f};
    #pragma unroll
    for (int ks=0; ks<4; ks++){
      unsigned bgo = SW128((unsigned)((8*nt+brow)*128 + (2*ks+bchk)*16));
      unsigned bso = SW128((unsigned)((8*(nt+8)+brow)*128 + (2*ks+bchk)*16));
      unsigned bh[2], bl[2];
      ldsm2(bh, WgHiB+bgo); ldsm2(bl, WgLoB+bgo);
      mma16816(accg, ah[ks], bh);
      mma16816(accg, al[ks], bh);
      mma16816(accg, ah[ks], bl);
      ldsm2(bh, WgHiB+bso); ldsm2(bl, WgLoB+bso);
      mma16816(accs, ah[ks], bh);
      mma16816(accs, al[ks], bh);
      mma16816(accs, ah[ks], bl);
    }
    const int ch0 = 8*nt + 2*(lane&3), ch1 = ch0+1;
    const float dv0 = s_dvec[ch0], dv1 = s_dvec[ch1];
    #pragma unroll
    for (int rp=0; rp<2; rp++){
      const int pxl = Mb + (lane>>2) + rp*8;
      float base0, base1;
      if (boundary){
        const long p = p0 + pxl;
        float d0=0.f, d1=0.f;
        for (int s=0;s<16;s++){
          float sv = g_Sp[(b*DSTATE+s)*CUT + p];
          d0 = fmaf(s_wC[ch0*16+s], sv, d0);
          d1 = fmaf(s_wC[ch1*16+s], sv, d1);
        }
        base0=d0; base1=d1;
      } else { base0 = s_cvec[ch0]; base1 = s_cvec[ch1]; }
      float xc0 = xcb[(long)ch0*LL + pxl];
      float xc1 = xcb[(long)ch1*LL + pxl];
      float g0 = fmaf(accg[2*rp],   s_gsc[ch0], s_gbe[ch0]);
      float g1 = fmaf(accg[2*rp+1], s_gsc[ch1], s_gbe[ch1]);
      float h0 = fmaf(accs[2*rp],   s_gsc[64+ch0], s_gbe[64+ch0]);
      float h1 = fmaf(accs[2*rp+1], s_gsc[64+ch1], s_gbe[64+ch1]);
      float v0 = fsig(g0)*(fmaf(dv0, xc0, base0) + ftanh(h0));
      float v1 = fsig(g1)*(fmaf(dv1, xc1, base1) + ftanh(h1));
      unsigned hi, lo;
      split2t(v0, v1, hi, lo);
      unsigned off = SW128((unsigned)(pxl*128 + ch0*2));
      *(unsigned*)(Ahi+off) = hi;
      *(unsigned*)(Alo+off) = lo;
    }
  }
  __syncwarp();   // own-warp STS -> LDSM visibility (rows are warp-private)

  // out GEMM: reload A fragments (xg), reuse regs
  #pragma unroll
  for (int ks=0; ks<4; ks++){
    unsigned aoff = SW128((unsigned)((Mb+arow)*128 + (2*ks+achk)*16));
    ldsm4(ah[ks], AhiB+aoff);
    ldsm4(al[ks], AloB+aoff);
  }
  float acc2[8][4];
  #pragma unroll
  for (int nt=0;nt<8;nt++)
    #pragma unroll
    for (int r=0;r<4;r++) acc2[nt][r]=0.f;
  #pragma unroll
  for (int ks=0; ks<4; ks++){
    #pragma unroll
    for (int nt=0; nt<8; nt++){
      unsigned boff = SW128((unsigned)((8*nt+brow)*128 + (2*ks+bchk)*16));
      unsigned bh[2], bl[2];
      ldsm2(bh, WoHiB+boff);
      ldsm2(bl, WoLoB+boff);
      mma16816(acc2[nt], ah[ks], bh);
      mma16816(acc2[nt], al[ks], bh);
      mma16816(acc2[nt], ah[ks], bl);
    }
  }
  __syncthreads();   // everyone done with Wg (reused as 'so') and own work

  float* so = (float*)(base + 32768);   // [64][132] = 33.8KB over WgHi/WgLo
  {
    int m = Mb + (lane>>2);
    #pragma unroll
    for (int nt=0;nt<8;nt++){
      int n = 8*nt + 2*(lane&3);
      so[n*132 + m]        = acc2[nt][0];
      so[(n+1)*132 + m]    = acc2[nt][1];
      so[n*132 + m + 8]    = acc2[nt][2];
      so[(n+1)*132 + m + 8]= acc2[nt][3];
    }
  }
  __syncthreads();

  float* dst = out + (long)b*CH*LL + p0;
  #pragma unroll
  for (int r=0;r<8;r++){
    int f4 = tid + r*256;
    int ch = f4>>5, px = (f4&31)<<2;
    float4 v = *(float4*)(so + ch*132 + px);
    float sc = s_osc[ch], be = s_obe[ch];
    float4 o = make_float4(fmaf(v.x,sc,be), fmaf(v.y,sc,be),
                           fmaf(v.z,sc,be), fmaf(v.w,sc,be));
    *(float4*)(dst + (long)ch*LL + px) = o;
  }
}

// ---------------------------------------------------------------------------
extern "C" void kernel_launch(void* const* d_in, const int* in_sizes, int n_in,
                              void* d_out, int out_size)
{
  const float* x    = (const float*)d_in[0];
  const float* w_in = (const float*)d_in[1];
  const float* gin  = (const float*)d_in[2];
  const float* bin  = (const float*)d_in[3];
  const float* wdw  = (const float*)d_in[4];
  const float* gcv  = (const float*)d_in[5];
  const float* bcv  = (const float*)d_in[6];
  const float* wB   = (const float*)d_in[7];
  const float* wC   = (const float*)d_in[8];
  const float* A    = (const float*)d_in[9];
  const float* Dv   = (const float*)d_in[10];
  const float* wg   = (const float*)d_in[11];
  const float* gg   = (const float*)d_in[12];
  const float* bg   = (const float*)d_in[13];
  const float* wo   = (const float*)d_in[14];
  const float* go   = (const float*)d_in[15];
  const float* bo   = (const float*)d_in[16];
  float* out = (float*)d_out;

  const int SM1 = 81920 + 1024;
  const int SM4 = 81920 + 1024;
  cudaFuncSetAttribute(k_inproj, cudaFuncAttributeMaxDynamicSharedMemorySize, SM1);
  cudaFuncSetAttribute(k_final,  cudaFuncAttributeMaxDynamicSharedMemorySize, SM4);

  k_prep  <<<1, 256>>>(w_in, wg, wo);
  k_inproj<<<dim3(LL/256, BATCH), 256, SM1>>>(x, gin, bin);
  k_dwconv<<<dim3(HH/16, CH, BATCH), 128>>>(wdw, gcv, bcv);
  k_bproj <<<dim3(CUT/128, BATCH), 128>>>(wB);
  k_scan  <<<BATCH*DSTATE, 256>>>(A);
  k_cproj <<<1, 512>>>(wC);
  k_final <<<dim3(LL/128, BATCH), 256, SM4>>>(wC, Dv, gg, bg, go, bo, out);
}